// round 15
// baseline (speedup 1.0000x reference)
#include <cuda_runtime.h>
#include <cuda_fp16.h>
#include <math.h>
#include <stdint.h>

#define BATCH 8
#define CDIM 192
#define C3 576
#define HWD 16384
#define HEADS 4
#define CH 48
#define NCHUNK 32
#define CHUNKPX 512

typedef unsigned long long ull;

// ---- fp16 mma m16n8k16, fp32 accumulate ----
__device__ __forceinline__ void mma_f16(float* c, uint4 a, uint2 b) {
    asm volatile(
        "mma.sync.aligned.m16n8k16.row.col.f32.f16.f16.f32 "
        "{%0,%1,%2,%3}, {%4,%5,%6,%7}, {%8,%9}, {%0,%1,%2,%3};"
        : "+f"(c[0]), "+f"(c[1]), "+f"(c[2]), "+f"(c[3])
        : "r"(a.x), "r"(a.y), "r"(a.z), "r"(a.w), "r"(b.x), "r"(b.y));
}
__device__ __forceinline__ uint32_t h2pack(float a, float b) {
    __half2 h = __floats2half2_rn(a, b);
    return *(uint32_t*)&h;
}

// ---- cp.async helpers ----
__device__ __forceinline__ void cp16(void* dst, const void* src) {
    uint32_t d;
    asm("{ .reg .u64 t; cvta.to.shared.u64 t, %1; cvt.u32.u64 %0, t; }" : "=r"(d) : "l"(dst));
    asm volatile("cp.async.cg.shared.global [%0], [%1], 16;" :: "r"(d), "l"(src) : "memory");
}
#define CP_COMMIT() asm volatile("cp.async.commit_group;" ::: "memory")
#define CP_WAIT(n)  asm volatile("cp.async.wait_group %0;" :: "n"(n) : "memory")

// ---- typed 4-element loads / 2-element stores ----
__device__ __forceinline__ float4 load4(const float* p) { return *(const float4*)p; }
__device__ __forceinline__ float4 load4(const __half* p) {
    __half2 h0 = *(const __half2*)p;
    __half2 h1 = *(const __half2*)(p + 2);
    float2 a = __half22float2(h0), b = __half22float2(h1);
    return make_float4(a.x, a.y, b.x, b.y);
}
__device__ __forceinline__ void store2(float* p, float a, float b) {
    *(float2*)p = make_float2(a, b);
}
__device__ __forceinline__ void store2(__half* p, float a, float b) {
    *(__half2*)p = __floats2half2_rn(a, b);
}

// ---- scratch (device globals; no allocations allowed) ----
__device__ __half g_qkv [(size_t)BATCH * C3 * HWD];
__device__ __half g_qkv2[(size_t)BATCH * C3 * HWD];
__device__ float g_part_gram[(size_t)BATCH * HEADS * NCHUNK * CH * CH];
__device__ float g_norm[(size_t)BATCH * C3];            // per (b,c) sum of squares
__device__ uint32_t g_apq[5 * 12288];          // qkv W, fp16 fragment-permuted
__device__ uint32_t g_apm[BATCH * 2 * 12288];  // combined proj@attn, per batch

// ============================================================
// Permute W[M,192] into fp16 m16n8k16 fragment order.
// ============================================================
__global__ __launch_bounds__(256) void prep_a(
    const float* __restrict__ W, uint32_t* __restrict__ Ap, int Mdim)
{
    const int idx = blockIdx.x * 256 + threadIdx.x;
    const int lane = idx & 31;
    int rest = idx >> 5;
    const int m16 = rest & 7; rest >>= 3;
    const int k16 = rest % 12;
    const int mt = rest / 12;
    const int g = lane >> 2, t = lane & 3;
    const int row = mt * 128 + m16 * 16 + g;
    const int k = k16 * 16 + 2 * t;
    float a00 = 0.f, a01 = 0.f, a10 = 0.f, a11 = 0.f;
    float a20 = 0.f, a21 = 0.f, a30 = 0.f, a31 = 0.f;
    if (row < Mdim) {
        const float* wr = W + (size_t)row * CDIM + k;
        a00 = wr[0]; a01 = wr[1]; a20 = wr[8]; a21 = wr[9];
    }
    if (row + 8 < Mdim) {
        const float* wr = W + (size_t)(row + 8) * CDIM + k;
        a10 = wr[0]; a11 = wr[1]; a30 = wr[8]; a31 = wr[9];
    }
    uint4 o;
    o.x = h2pack(a00, a01); o.y = h2pack(a10, a11);
    o.z = h2pack(a20, a21); o.w = h2pack(a30, a31);
    *(uint4*)(Ap + (size_t)idx * 4) = o;
}

// ============================================================
// Pointwise GEMM via mma.sync fp16: Y[b,m,n] = sum_k A[(b),m,k] X[b,k,n]
// 128x128 block, BK=32, double buffered, cp.async A staging.
// Ragged M: MMAs for m16 groups past Mdim are skipped (A rows are zero
// padded, outputs discarded — exact).
// ============================================================
template <typename InT, typename OutT>
__global__ __launch_bounds__(256) void pw_mma(
    const uint32_t* __restrict__ Ap, size_t a_bstride,
    const InT* __restrict__ X, size_t x_bstride,
    OutT* __restrict__ Y, size_t y_bstride, int Mdim)
{
    __shared__ __align__(16) uint32_t As[2][2048];
    __shared__ __align__(16) uint32_t Bs16[2][16 * 136];
    const int tid = threadIdx.x;
    const int lane = tid & 31, wid = tid >> 5;
    const int mt = blockIdx.x;
    const int n0 = blockIdx.y * 128;
    const size_t boffX = (size_t)blockIdx.z * x_bstride;
    const size_t boffY = (size_t)blockIdx.z * y_bstride;

    const uint32_t* apg = Ap + (size_t)blockIdx.z * a_bstride + (size_t)mt * 12288;
    const int nq = tid & 31;
    const int bk0 = tid >> 5;

    float4 b_r0, b_r1, b_r2, b_r3;

    auto cpa_iter = [&](int it, int buf) {
        const uint32_t* ap = apg + (size_t)it * 2048 + tid * 8;
        cp16(&As[buf][tid * 8], ap);
        cp16(&As[buf][tid * 8 + 4], ap + 4);
    };
    auto ldgb_iter = [&](int it) {
        const InT* xb = X + boffX + (size_t)(it * 32 + 2 * bk0) * HWD + n0 + nq * 4;
        b_r0 = load4(xb);
        b_r1 = load4(xb + HWD);
        b_r2 = load4(xb + (size_t)16 * HWD);
        b_r3 = load4(xb + (size_t)17 * HWD);
    };
    auto stsb_iter = [&](int buf) {
        uint4 p0, p1;
        p0.x = h2pack(b_r0.x, b_r1.x); p0.y = h2pack(b_r0.y, b_r1.y);
        p0.z = h2pack(b_r0.z, b_r1.z); p0.w = h2pack(b_r0.w, b_r1.w);
        p1.x = h2pack(b_r2.x, b_r3.x); p1.y = h2pack(b_r2.y, b_r3.y);
        p1.z = h2pack(b_r2.z, b_r3.z); p1.w = h2pack(b_r2.w, b_r3.w);
        *(uint4*)&Bs16[buf][bk0 * 136 + nq * 4] = p0;
        *(uint4*)&Bs16[buf][(8 + bk0) * 136 + nq * 4] = p1;
    };

    float acc[2][8][4];
#pragma unroll
    for (int f = 0; f < 2; f++)
#pragma unroll
        for (int j = 0; j < 8; j++)
#pragma unroll
            for (int e = 0; e < 4; e++) acc[f][j][e] = 0.f;

    const int m16a = (wid & 3) * 2;
    const int t = lane & 3;
    const int g = lane >> 2;
    const int nwb = (wid >> 2) * 64;
    // ragged-M: does this warp's m16 group contain real rows?
    const bool do0 = (mt * 128 + m16a * 16) < Mdim;
    const bool do1 = (mt * 128 + (m16a + 1) * 16) < Mdim;

    auto compute = [&](int buf) {
#pragma unroll
        for (int s = 0; s < 2; s++) {
            const int br0 = (s * 8 + t) * 136 + nwb + g;
            const int br1 = (s * 8 + t + 4) * 136 + nwb + g;
            if (do0) {
                uint4 A0 = *(const uint4*)&As[buf][(s * 256 + m16a * 32 + lane) * 4];
#pragma unroll
                for (int j = 0; j < 8; j++) {
                    uint2 b = make_uint2(Bs16[buf][br0 + j * 8], Bs16[buf][br1 + j * 8]);
                    mma_f16(acc[0][j], A0, b);
                }
            }
            if (do1) {
                uint4 A1 = *(const uint4*)&As[buf][(s * 256 + (m16a + 1) * 32 + lane) * 4];
#pragma unroll
                for (int j = 0; j < 8; j++) {
                    uint2 b = make_uint2(Bs16[buf][br0 + j * 8], Bs16[buf][br1 + j * 8]);
                    mma_f16(acc[1][j], A1, b);
                }
            }
        }
    };

    cpa_iter(0, 0);
    ldgb_iter(0);
    CP_COMMIT();
    stsb_iter(0);
    CP_WAIT(0);
    __syncthreads();
#pragma unroll 1
    for (int it = 0; it < 6; it++) {
        if (it + 1 < 6) {
            cpa_iter(it + 1, (it + 1) & 1);
            ldgb_iter(it + 1);
            CP_COMMIT();
        }
        compute(it & 1);
        if (it + 1 < 6) stsb_iter((it + 1) & 1);
        CP_WAIT(0);
        __syncthreads();
    }

    const int mw = mt * 128 + (wid & 3) * 32;
#pragma unroll
    for (int f = 0; f < 2; f++) {
        const int m = mw + f * 16 + g;
#pragma unroll
        for (int j = 0; j < 8; j++) {
            OutT* p = Y + boffY + (size_t)m * HWD + n0 + nwb + j * 8 + 2 * t;
            if (m < Mdim)
                store2(p, acc[f][j][0], acc[f][j][1]);
            if (m + 8 < Mdim)
                store2(p + (size_t)8 * HWD, acc[f][j][2], acc[f][j][3]);
        }
    }
}

// ============================================================
// Depthwise 3x3, pad 1 — register sliding window + shuffle halos.
// One block per (b,c) image; warp = 16-row strip. Emits per-channel
// sum-of-squares (fp32, deterministic) for Q/K channels.
// ============================================================
__global__ __launch_bounds__(256) void dw_conv_kernel(
    const __half* __restrict__ in, const float* __restrict__ wts,
    __half* __restrict__ out)
{
    const int bc = blockIdx.x;
    const int c = bc % C3;
    const int warp = threadIdx.x >> 5;
    const int lane = threadIdx.x & 31;
    const int y0 = warp * 16;

    float w[9];
#pragma unroll
    for (int i = 0; i < 9; i++) w[i] = __ldg(wts + c * 9 + i);

    const __half* ip = in + (size_t)bc * HWD + lane * 4;
    float win[3][6];

    auto loadrow = [&](int gy, float* row6) {
        float4 v = make_float4(0.f, 0.f, 0.f, 0.f);
        if (gy >= 0 && gy < 128) v = load4(ip + (size_t)gy * 128);
        float l = __shfl_up_sync(0xffffffffu, v.w, 1);
        float r = __shfl_down_sync(0xffffffffu, v.x, 1);
        if (lane == 0)  l = 0.f;
        if (lane == 31) r = 0.f;
        row6[0] = l; row6[1] = v.x; row6[2] = v.y;
        row6[3] = v.z; row6[4] = v.w; row6[5] = r;
    };

    loadrow(y0 - 1, win[0]);
    loadrow(y0,     win[1]);
    __half* op = out + (size_t)bc * HWD + lane * 4;
    float ns = 0.f;
#pragma unroll
    for (int r = 0; r < 16; r++) {
        loadrow(y0 + 1 + r, win[(r + 2) % 3]);
        const float* tp = win[r % 3];
        const float* mp = win[(r + 1) % 3];
        const float* bp = win[(r + 2) % 3];
        float o[4];
#pragma unroll
        for (int p = 0; p < 4; p++) {
            float s = 0.f;
            s = fmaf(tp[p], w[0], s); s = fmaf(tp[p + 1], w[1], s); s = fmaf(tp[p + 2], w[2], s);
            s = fmaf(mp[p], w[3], s); s = fmaf(mp[p + 1], w[4], s); s = fmaf(mp[p + 2], w[5], s);
            s = fmaf(bp[p], w[6], s); s = fmaf(bp[p + 1], w[7], s); s = fmaf(bp[p + 2], w[8], s);
            o[p] = s;
            ns = fmaf(s, s, ns);
        }
        __half2 h0 = __floats2half2_rn(o[0], o[1]);
        __half2 h1 = __floats2half2_rn(o[2], o[3]);
        __half2* dst = (__half2*)(op + (size_t)(y0 + r) * 128);
        dst[0] = h0; dst[1] = h1;
    }

    // deterministic block reduction of sum-of-squares (Q/K channels only)
    if (c < 2 * CDIM) {
        __shared__ float red[8];
#pragma unroll
        for (int o = 16; o; o >>= 1) ns += __shfl_xor_sync(0xffffffffu, ns, o);
        if (lane == 0) red[warp] = ns;
        __syncthreads();
        if (threadIdx.x == 0) {
            float s = 0.f;
#pragma unroll
            for (int i = 0; i < 8; i++) s += red[i];
            g_norm[bc] = s;
        }
    }
}

// ============================================================
// Gram on fp16 tensor cores: Q@K^T (48x48) per (bh, 512-px chunk).
// cp.async raw staging, double-buffered.
// ============================================================
__global__ __launch_bounds__(256) void gram_kernel()
{
    const int chunk = blockIdx.x;
    const int bh = blockIdx.y;
    const int b = bh >> 2, h = bh & 3;
    const __half* qb = g_qkv2 + ((size_t)b * C3 + h * CH) * HWD;
    const __half* kb = g_qkv2 + ((size_t)b * C3 + CDIM + h * CH) * HWD;
    __shared__ __align__(16) __half Qs[2][CH][72];
    __shared__ __align__(16) __half Ks[2][CH][72];
    const int tid = threadIdx.x;
    const int lane = tid & 31, wid = tid >> 5;
    const int n0 = chunk * CHUNKPX;

    float acc[3][4];
#pragma unroll
    for (int jj = 0; jj < 3; jj++)
#pragma unroll
        for (int e = 0; e < 4; e++) acc[jj][e] = 0.f;

    const int mrow = wid % 3;
    const int nhalf = (wid < 6) ? (wid / 3) : 0;
    const int g = lane >> 2, t = lane & 3;

    const __half* sbase = (tid < 128) ? qb : kb;
    const int st = tid & 127;

    auto stage = [&](int t0, int buf) {
        __half (*dst)[72] = (tid < 128) ? Qs[buf] : Ks[buf];
#pragma unroll
        for (int i = 0; i < 3; i++) {
            int idx = i * 128 + st;
            int row = idx >> 3, cg = idx & 7;
            cp16(&dst[row][cg * 8], sbase + (size_t)row * HWD + n0 + t0 + cg * 8);
        }
    };

    const int NTILE = CHUNKPX / 64;
    stage(0, 0);
    CP_COMMIT();
#pragma unroll 1
    for (int ti = 0; ti < NTILE; ti++) {
        if (ti + 1 < NTILE) {
            stage((ti + 1) * 64, (ti + 1) & 1);
            CP_COMMIT();
            CP_WAIT(1);
        } else {
            CP_WAIT(0);
        }
        __syncthreads();
        if (wid < 6) {
            const int buf = ti & 1;
            const int mr = 16 * mrow + g;
#pragma unroll
            for (int s = 0; s < 4; s++) {
                const int kh = s * 16 + 2 * t;
                uint4 a;
                a.x = *(const uint32_t*)&Qs[buf][mr][kh];
                a.y = *(const uint32_t*)&Qs[buf][mr + 8][kh];
                a.z = *(const uint32_t*)&Qs[buf][mr][kh + 8];
                a.w = *(const uint32_t*)&Qs[buf][mr + 8][kh + 8];
#pragma unroll
                for (int jj = 0; jj < 3; jj++) {
                    const int nr = 8 * (3 * nhalf + jj) + g;
                    uint2 bf = make_uint2(*(const uint32_t*)&Ks[buf][nr][kh],
                                          *(const uint32_t*)&Ks[buf][nr][kh + 8]);
                    mma_f16(acc[jj], a, bf);
                }
            }
        }
        __syncthreads();
    }

    if (wid < 6) {
        float* gp = g_part_gram + ((size_t)bh * NCHUNK + chunk) * CH * CH;
        const int m = 16 * mrow + g;
#pragma unroll
        for (int jj = 0; jj < 3; jj++) {
            const int n = 8 * (3 * nhalf + jj) + 2 * t;
            *(float2*)&gp[m * CH + n] = make_float2(acc[jj][0], acc[jj][1]);
            *(float2*)&gp[(m + 8) * CH + n] = make_float2(acc[jj][2], acc[jj][3]);
        }
    }
}

// ============================================================
// Fused: reduce partials -> normalize -> softmax -> combine with proj
// -> emit fragment-permuted fp16 apm directly.
// ============================================================
__global__ __launch_bounds__(256) void attn_combine_kernel(
    const float* __restrict__ temperature, const float* __restrict__ P,
    uint32_t* __restrict__ apm)
{
    const int bh = blockIdx.x;
    const int b = bh >> 2, h = bh & 3;
    __shared__ float S[CH * CH];
    __shared__ float A[CH * CH];
    __shared__ float rq[CH];
    __shared__ float rk[CH];
    const int tid = threadIdx.x;
    const int lane = tid & 31, wid = tid >> 5;

    for (int e = tid; e < CH * CH; e += 256) {
        float s = 0.f;
#pragma unroll
        for (int p = 0; p < NCHUNK; p++)
            s += g_part_gram[((size_t)bh * NCHUNK + p) * CH * CH + e];
        S[e] = s;
    }
    if (tid < CH) {
        rq[tid] = fmaxf(sqrtf(g_norm[b * C3 + h * CH + tid]), 1e-12f);
    } else if (tid < 2 * CH) {
        rk[tid - CH] = fmaxf(sqrtf(g_norm[b * C3 + CDIM + h * CH + (tid - CH)]), 1e-12f);
    }
    __syncthreads();

    // warp-parallel softmax: warp w -> rows 6w..6w+5, lanes split 48 cols
    const float tmp = temperature[h];
    const int c2 = lane + 32;
#pragma unroll
    for (int rr = 0; rr < 6; rr++) {
        const int r = wid * 6 + rr;
        const float fq = tmp / rq[r];
        float v1 = S[r * CH + lane] * fq / rk[lane];
        float v2 = (c2 < CH) ? S[r * CH + c2] * fq / rk[c2] : -1e30f;
        float mx = fmaxf(v1, v2);
#pragma unroll
        for (int o = 16; o; o >>= 1) mx = fmaxf(mx, __shfl_xor_sync(0xffffffffu, mx, o));
        float e1 = expf(v1 - mx);
        float e2 = (c2 < CH) ? expf(v2 - mx) : 0.f;
        float sm = e1 + e2;
#pragma unroll
        for (int o = 16; o; o >>= 1) sm += __shfl_xor_sync(0xffffffffu, sm, o);
        float inv = 1.f / sm;
        A[r * CH + lane] = e1 * inv;
        if (c2 < CH) A[r * CH + c2] = e2 * inv;
    }
    __syncthreads();

    // combine + permute: thread m computes Comb row m for head h's 48 cols,
    // packs k-pairs to fp16 and scatters into mma fragment layout.
    if (tid < CDIM) {
        const int m = tid;
        float p[CH];
#pragma unroll
        for (int c = 0; c < CH; c++) p[c] = P[(size_t)m * CDIM + h * CH + c];
        float o[CH];
#pragma unroll 4
        for (int d = 0; d < CH; d++) {
            float s = 0.f;
#pragma unroll
            for (int c = 0; c < CH; c++) s = fmaf(p[c], A[c * CH + d], s);
            o[d] = s;
        }
        const int mt = m >> 7;
        const int m16 = (m & 127) >> 4;
        const int gg = m & 7;
        const int hi = (m & 15) >> 3;
        uint32_t* base = apm + (size_t)b * 24576 + mt * 12288 + m16 * 128;
#pragma unroll
        for (int d2 = 0; d2 < CH / 2; d2++) {
            const int k = h * CH + 2 * d2;
            const int k16 = k >> 4;
            const int rem = k & 15;
            const int t = (rem & 7) >> 1;
            const int reg = (rem >> 3) * 2 + hi;
            base[k16 * 1024 + (gg * 4 + t) * 4 + reg] = h2pack(o[2 * d2], o[2 * d2 + 1]);
        }
    }
}

// ============================================================
extern "C" void kernel_launch(void* const* d_in, const int* in_sizes, int n_in,
                              void* d_out, int out_size)
{
    const float* x      = (const float*)d_in[0];
    const float* qkv_w  = (const float*)d_in[1];
    const float* dw_w   = (const float*)d_in[2];
    const float* proj_w = (const float*)d_in[3];
    const float* temp   = (const float*)d_in[4];
    float* out = (float*)d_out;

    __half *qkv, *qkv2;
    uint32_t *apq, *apm;
    cudaGetSymbolAddress((void**)&qkv,  g_qkv);
    cudaGetSymbolAddress((void**)&qkv2, g_qkv2);
    cudaGetSymbolAddress((void**)&apq,  g_apq);
    cudaGetSymbolAddress((void**)&apm,  g_apm);

    dim3 blk(256);
    // 0) permute + fp16-convert qkv weights
    prep_a<<<60, blk>>>(qkv_w, apq, C3);
    // 1) qkv 1x1 conv (fp16 tensor cores, ragged-M skip)
    pw_mma<float, __half><<<dim3(5, 128, BATCH), blk>>>(
        apq, 0, x, (size_t)CDIM * HWD, qkv, (size_t)C3 * HWD, C3);
    // 2) depthwise 3x3 + Q/K norms (one block per image)
    dw_conv_kernel<<<BATCH * C3, blk>>>(qkv, dw_w, qkv2);
    // 3) Q@K^T partials (fp16 tensor cores, cp.async staging)
    gram_kernel<<<dim3(NCHUNK, BATCH * HEADS), blk>>>();
    // 4) softmax + fold into proj weights + fragment-permute (fused)
    attn_combine_kernel<<<BATCH * HEADS, blk>>>(temp, proj_w, apm);
    // 5) fused (proj @ attn) @ v -> d_out (ragged-M skip)
    pw_mma<__half, float><<<dim3(2, 128, BATCH), blk>>>(
        apm, 24576, qkv2 + (size_t)2 * CDIM * HWD, (size_t)C3 * HWD,
        out, (size_t)CDIM * HWD, CDIM);
}

// round 16
// speedup vs baseline: 1.0598x; 1.0598x over previous
#include <cuda_runtime.h>
#include <cuda_fp16.h>
#include <math.h>
#include <stdint.h>

#define BATCH 8
#define CDIM 192
#define C3 576
#define HWD 16384
#define HEADS 4
#define CH 48
#define NCHUNK 32
#define CHUNKPX 512

typedef unsigned long long ull;

// ---- fp16 mma m16n8k16, fp32 accumulate ----
__device__ __forceinline__ void mma_f16(float* c, uint4 a, uint2 b) {
    asm volatile(
        "mma.sync.aligned.m16n8k16.row.col.f32.f16.f16.f32 "
        "{%0,%1,%2,%3}, {%4,%5,%6,%7}, {%8,%9}, {%0,%1,%2,%3};"
        : "+f"(c[0]), "+f"(c[1]), "+f"(c[2]), "+f"(c[3])
        : "r"(a.x), "r"(a.y), "r"(a.z), "r"(a.w), "r"(b.x), "r"(b.y));
}
__device__ __forceinline__ uint32_t h2pack(float a, float b) {
    __half2 h = __floats2half2_rn(a, b);
    return *(uint32_t*)&h;
}

// ---- cp.async helpers ----
__device__ __forceinline__ void cp16(void* dst, const void* src) {
    uint32_t d;
    asm("{ .reg .u64 t; cvta.to.shared.u64 t, %1; cvt.u32.u64 %0, t; }" : "=r"(d) : "l"(dst));
    asm volatile("cp.async.cg.shared.global [%0], [%1], 16;" :: "r"(d), "l"(src) : "memory");
}
#define CP_COMMIT() asm volatile("cp.async.commit_group;" ::: "memory")
#define CP_WAIT(n)  asm volatile("cp.async.wait_group %0;" :: "n"(n) : "memory")

// ---- typed 4-element loads / 2-element stores ----
__device__ __forceinline__ float4 load4(const float* p) { return *(const float4*)p; }
__device__ __forceinline__ float4 load4(const __half* p) {
    __half2 h0 = *(const __half2*)p;
    __half2 h1 = *(const __half2*)(p + 2);
    float2 a = __half22float2(h0), b = __half22float2(h1);
    return make_float4(a.x, a.y, b.x, b.y);
}
__device__ __forceinline__ void store2(float* p, float a, float b) {
    *(float2*)p = make_float2(a, b);
}
__device__ __forceinline__ void store2(__half* p, float a, float b) {
    *(__half2*)p = __floats2half2_rn(a, b);
}

// ---- scratch (device globals; no allocations allowed) ----
__device__ __half g_qkv [(size_t)BATCH * C3 * HWD];
__device__ __half g_qkv2[(size_t)BATCH * C3 * HWD];
__device__ float g_part_gram[(size_t)BATCH * HEADS * NCHUNK * CH * CH];
__device__ float g_norm_part[(size_t)BATCH * C3 * 2];   // per (b,c): 2 block partials
__device__ uint32_t g_apq[5 * 12288];          // qkv W, fp16 fragment-permuted
__device__ uint32_t g_apm[BATCH * 2 * 12288];  // combined proj@attn, per batch

// ============================================================
// Permute W[M,192] into fp16 m16n8k16 fragment order.
// ============================================================
__global__ __launch_bounds__(256) void prep_a(
    const float* __restrict__ W, uint32_t* __restrict__ Ap, int Mdim)
{
    const int idx = blockIdx.x * 256 + threadIdx.x;
    const int lane = idx & 31;
    int rest = idx >> 5;
    const int m16 = rest & 7; rest >>= 3;
    const int k16 = rest % 12;
    const int mt = rest / 12;
    const int g = lane >> 2, t = lane & 3;
    const int row = mt * 128 + m16 * 16 + g;
    const int k = k16 * 16 + 2 * t;
    float a00 = 0.f, a01 = 0.f, a10 = 0.f, a11 = 0.f;
    float a20 = 0.f, a21 = 0.f, a30 = 0.f, a31 = 0.f;
    if (row < Mdim) {
        const float* wr = W + (size_t)row * CDIM + k;
        a00 = wr[0]; a01 = wr[1]; a20 = wr[8]; a21 = wr[9];
    }
    if (row + 8 < Mdim) {
        const float* wr = W + (size_t)(row + 8) * CDIM + k;
        a10 = wr[0]; a11 = wr[1]; a30 = wr[8]; a31 = wr[9];
    }
    uint4 o;
    o.x = h2pack(a00, a01); o.y = h2pack(a10, a11);
    o.z = h2pack(a20, a21); o.w = h2pack(a30, a31);
    *(uint4*)(Ap + (size_t)idx * 4) = o;
}

// ============================================================
// Pointwise GEMM via mma.sync fp16: Y[b,m,n] = sum_k A[(b),m,k] X[b,k,n]
// 128x128 block, BK=32, double buffered; A tile staged via cp.async.
// Block-uniform two-path dispatch: full tiles run the R14 code path
// unchanged; ragged tiles (past Mdim) skip zero-row MMAs (exact).
// ============================================================
template <typename InT, typename OutT>
__global__ __launch_bounds__(256) void pw_mma(
    const uint32_t* __restrict__ Ap, size_t a_bstride,
    const InT* __restrict__ X, size_t x_bstride,
    OutT* __restrict__ Y, size_t y_bstride, int Mdim)
{
    __shared__ __align__(16) uint32_t As[2][2048];
    __shared__ __align__(16) uint32_t Bs16[2][16 * 136];
    const int tid = threadIdx.x;
    const int lane = tid & 31, wid = tid >> 5;
    const int mt = blockIdx.x;
    const int n0 = blockIdx.y * 128;
    const size_t boffX = (size_t)blockIdx.z * x_bstride;
    const size_t boffY = (size_t)blockIdx.z * y_bstride;

    const uint32_t* apg = Ap + (size_t)blockIdx.z * a_bstride + (size_t)mt * 12288;
    const int nq = tid & 31;
    const int bk0 = tid >> 5;

    float4 b_r0, b_r1, b_r2, b_r3;

    auto cpa_iter = [&](int it, int buf) {
        const uint32_t* ap = apg + (size_t)it * 2048 + tid * 8;
        cp16(&As[buf][tid * 8], ap);
        cp16(&As[buf][tid * 8 + 4], ap + 4);
    };
    auto ldgb_iter = [&](int it) {
        const InT* xb = X + boffX + (size_t)(it * 32 + 2 * bk0) * HWD + n0 + nq * 4;
        b_r0 = load4(xb);
        b_r1 = load4(xb + HWD);
        b_r2 = load4(xb + (size_t)16 * HWD);
        b_r3 = load4(xb + (size_t)17 * HWD);
    };
    auto stsb_iter = [&](int buf) {
        uint4 p0, p1;
        p0.x = h2pack(b_r0.x, b_r1.x); p0.y = h2pack(b_r0.y, b_r1.y);
        p0.z = h2pack(b_r0.z, b_r1.z); p0.w = h2pack(b_r0.w, b_r1.w);
        p1.x = h2pack(b_r2.x, b_r3.x); p1.y = h2pack(b_r2.y, b_r3.y);
        p1.z = h2pack(b_r2.z, b_r3.z); p1.w = h2pack(b_r2.w, b_r3.w);
        *(uint4*)&Bs16[buf][bk0 * 136 + nq * 4] = p0;
        *(uint4*)&Bs16[buf][(8 + bk0) * 136 + nq * 4] = p1;
    };

    float acc[2][8][4];
#pragma unroll
    for (int f = 0; f < 2; f++)
#pragma unroll
        for (int j = 0; j < 8; j++)
#pragma unroll
            for (int e = 0; e < 4; e++) acc[f][j][e] = 0.f;

    const int m16a = (wid & 3) * 2;
    const int t = lane & 3;
    const int g = lane >> 2;
    const int nwb = (wid >> 2) * 64;
    // block-uniform: is this whole 128-row tile inside Mdim?
    const bool tile_full = (mt * 128 + 128) <= Mdim;
    const bool do0 = (mt * 128 + m16a * 16) < Mdim;
    const bool do1 = (mt * 128 + (m16a + 1) * 16) < Mdim;

    // R14-identical fast path
    auto compute_full = [&](int buf) {
#pragma unroll
        for (int s = 0; s < 2; s++) {
            uint4 A0 = *(const uint4*)&As[buf][(s * 256 + m16a * 32 + lane) * 4];
            uint4 A1 = *(const uint4*)&As[buf][(s * 256 + (m16a + 1) * 32 + lane) * 4];
            const int br0 = (s * 8 + t) * 136 + nwb + g;
            const int br1 = (s * 8 + t + 4) * 136 + nwb + g;
#pragma unroll
            for (int j = 0; j < 8; j++) {
                uint2 b = make_uint2(Bs16[buf][br0 + j * 8], Bs16[buf][br1 + j * 8]);
                mma_f16(acc[0][j], A0, b);
                mma_f16(acc[1][j], A1, b);
            }
        }
    };
    // ragged path: skip m16 groups past Mdim (their A rows are zero,
    // outputs discarded)
    auto compute_ragged = [&](int buf) {
#pragma unroll
        for (int s = 0; s < 2; s++) {
            const int br0 = (s * 8 + t) * 136 + nwb + g;
            const int br1 = (s * 8 + t + 4) * 136 + nwb + g;
            if (do0) {
                uint4 A0 = *(const uint4*)&As[buf][(s * 256 + m16a * 32 + lane) * 4];
#pragma unroll
                for (int j = 0; j < 8; j++) {
                    uint2 b = make_uint2(Bs16[buf][br0 + j * 8], Bs16[buf][br1 + j * 8]);
                    mma_f16(acc[0][j], A0, b);
                }
            }
            if (do1) {
                uint4 A1 = *(const uint4*)&As[buf][(s * 256 + (m16a + 1) * 32 + lane) * 4];
#pragma unroll
                for (int j = 0; j < 8; j++) {
                    uint2 b = make_uint2(Bs16[buf][br0 + j * 8], Bs16[buf][br1 + j * 8]);
                    mma_f16(acc[1][j], A1, b);
                }
            }
        }
    };

    cpa_iter(0, 0);
    ldgb_iter(0);
    CP_COMMIT();
    stsb_iter(0);
    CP_WAIT(0);
    __syncthreads();
    if (tile_full) {
#pragma unroll 1
        for (int it = 0; it < 6; it++) {
            if (it + 1 < 6) {
                cpa_iter(it + 1, (it + 1) & 1);
                ldgb_iter(it + 1);
                CP_COMMIT();
            }
            compute_full(it & 1);
            if (it + 1 < 6) stsb_iter((it + 1) & 1);
            CP_WAIT(0);
            __syncthreads();
        }
    } else {
#pragma unroll 1
        for (int it = 0; it < 6; it++) {
            if (it + 1 < 6) {
                cpa_iter(it + 1, (it + 1) & 1);
                ldgb_iter(it + 1);
                CP_COMMIT();
            }
            compute_ragged(it & 1);
            if (it + 1 < 6) stsb_iter((it + 1) & 1);
            CP_WAIT(0);
            __syncthreads();
        }
    }

    const int mw = mt * 128 + (wid & 3) * 32;
#pragma unroll
    for (int f = 0; f < 2; f++) {
        const int m = mw + f * 16 + g;
#pragma unroll
        for (int j = 0; j < 8; j++) {
            OutT* p = Y + boffY + (size_t)m * HWD + n0 + nwb + j * 8 + 2 * t;
            if (m < Mdim)
                store2(p, acc[f][j][0], acc[f][j][1]);
            if (m + 8 < Mdim)
                store2(p + (size_t)8 * HWD, acc[f][j][2], acc[f][j][3]);
        }
    }
}

// ============================================================
// Depthwise 3x3, pad 1 — register sliding window + shuffle halos.
// (R14 structure: 8-row warp strips, grid (BATCH*C3, 2).)
// Emits per-channel sum-of-squares partials for Q/K channels.
// ============================================================
__global__ __launch_bounds__(256) void dw_conv_kernel(
    const __half* __restrict__ in, const float* __restrict__ wts,
    __half* __restrict__ out)
{
    const int bc = blockIdx.x;
    const int c = bc % C3;
    const int warp = threadIdx.x >> 5;
    const int lane = threadIdx.x & 31;
    const int y0 = blockIdx.y * 64 + warp * 8;

    float w[9];
#pragma unroll
    for (int i = 0; i < 9; i++) w[i] = __ldg(wts + c * 9 + i);

    const __half* ip = in + (size_t)bc * HWD + lane * 4;
    float win[3][6];

    auto loadrow = [&](int gy, float* row6) {
        float4 v = make_float4(0.f, 0.f, 0.f, 0.f);
        if (gy >= 0 && gy < 128) v = load4(ip + (size_t)gy * 128);
        float l = __shfl_up_sync(0xffffffffu, v.w, 1);
        float r = __shfl_down_sync(0xffffffffu, v.x, 1);
        if (lane == 0)  l = 0.f;
        if (lane == 31) r = 0.f;
        row6[0] = l; row6[1] = v.x; row6[2] = v.y;
        row6[3] = v.z; row6[4] = v.w; row6[5] = r;
    };

    loadrow(y0 - 1, win[0]);
    loadrow(y0,     win[1]);
    __half* op = out + (size_t)bc * HWD + lane * 4;
    float ns = 0.f;
#pragma unroll
    for (int r = 0; r < 8; r++) {
        loadrow(y0 + 1 + r, win[(r + 2) % 3]);
        const float* tp = win[r % 3];
        const float* mp = win[(r + 1) % 3];
        const float* bp = win[(r + 2) % 3];
        float o[4];
#pragma unroll
        for (int p = 0; p < 4; p++) {
            float s = 0.f;
            s = fmaf(tp[p], w[0], s); s = fmaf(tp[p + 1], w[1], s); s = fmaf(tp[p + 2], w[2], s);
            s = fmaf(mp[p], w[3], s); s = fmaf(mp[p + 1], w[4], s); s = fmaf(mp[p + 2], w[5], s);
            s = fmaf(bp[p], w[6], s); s = fmaf(bp[p + 1], w[7], s); s = fmaf(bp[p + 2], w[8], s);
            o[p] = s;
            ns = fmaf(s, s, ns);
        }
        __half2 h0 = __floats2half2_rn(o[0], o[1]);
        __half2 h1 = __floats2half2_rn(o[2], o[3]);
        __half2* dst = (__half2*)(op + (size_t)(y0 + r) * 128);
        dst[0] = h0; dst[1] = h1;
    }

    // deterministic block reduction of sum-of-squares (Q/K channels only)
    if (c < 2 * CDIM) {
        __shared__ float red[8];
#pragma unroll
        for (int o = 16; o; o >>= 1) ns += __shfl_xor_sync(0xffffffffu, ns, o);
        if (lane == 0) red[warp] = ns;
        __syncthreads();
        if (threadIdx.x == 0) {
            float s = 0.f;
#pragma unroll
            for (int i = 0; i < 8; i++) s += red[i];
            g_norm_part[(size_t)bc * 2 + blockIdx.y] = s;
        }
    }
}

// ============================================================
// Gram on fp16 tensor cores: Q@K^T (48x48) per (bh, 512-px chunk).
// cp.async raw staging, double-buffered. (R14, unchanged.)
// ============================================================
__global__ __launch_bounds__(256) void gram_kernel()
{
    const int chunk = blockIdx.x;
    const int bh = blockIdx.y;
    const int b = bh >> 2, h = bh & 3;
    const __half* qb = g_qkv2 + ((size_t)b * C3 + h * CH) * HWD;
    const __half* kb = g_qkv2 + ((size_t)b * C3 + CDIM + h * CH) * HWD;
    __shared__ __align__(16) __half Qs[2][CH][72];
    __shared__ __align__(16) __half Ks[2][CH][72];
    const int tid = threadIdx.x;
    const int lane = tid & 31, wid = tid >> 5;
    const int n0 = chunk * CHUNKPX;

    float acc[3][4];
#pragma unroll
    for (int jj = 0; jj < 3; jj++)
#pragma unroll
        for (int e = 0; e < 4; e++) acc[jj][e] = 0.f;

    const int mrow = wid % 3;
    const int nhalf = (wid < 6) ? (wid / 3) : 0;
    const int g = lane >> 2, t = lane & 3;

    const __half* sbase = (tid < 128) ? qb : kb;
    const int st = tid & 127;

    auto stage = [&](int t0, int buf) {
        __half (*dst)[72] = (tid < 128) ? Qs[buf] : Ks[buf];
#pragma unroll
        for (int i = 0; i < 3; i++) {
            int idx = i * 128 + st;
            int row = idx >> 3, cg = idx & 7;
            cp16(&dst[row][cg * 8], sbase + (size_t)row * HWD + n0 + t0 + cg * 8);
        }
    };

    const int NTILE = CHUNKPX / 64;
    stage(0, 0);
    CP_COMMIT();
#pragma unroll 1
    for (int ti = 0; ti < NTILE; ti++) {
        if (ti + 1 < NTILE) {
            stage((ti + 1) * 64, (ti + 1) & 1);
            CP_COMMIT();
            CP_WAIT(1);
        } else {
            CP_WAIT(0);
        }
        __syncthreads();
        if (wid < 6) {
            const int buf = ti & 1;
            const int mr = 16 * mrow + g;
#pragma unroll
            for (int s = 0; s < 4; s++) {
                const int kh = s * 16 + 2 * t;
                uint4 a;
                a.x = *(const uint32_t*)&Qs[buf][mr][kh];
                a.y = *(const uint32_t*)&Qs[buf][mr + 8][kh];
                a.z = *(const uint32_t*)&Qs[buf][mr][kh + 8];
                a.w = *(const uint32_t*)&Qs[buf][mr + 8][kh + 8];
#pragma unroll
                for (int jj = 0; jj < 3; jj++) {
                    const int nr = 8 * (3 * nhalf + jj) + g;
                    uint2 bf = make_uint2(*(const uint32_t*)&Ks[buf][nr][kh],
                                          *(const uint32_t*)&Ks[buf][nr][kh + 8]);
                    mma_f16(acc[jj], a, bf);
                }
            }
        }
        __syncthreads();
    }

    if (wid < 6) {
        float* gp = g_part_gram + ((size_t)bh * NCHUNK + chunk) * CH * CH;
        const int m = 16 * mrow + g;
#pragma unroll
        for (int jj = 0; jj < 3; jj++) {
            const int n = 8 * (3 * nhalf + jj) + 2 * t;
            *(float2*)&gp[m * CH + n] = make_float2(acc[jj][0], acc[jj][1]);
            *(float2*)&gp[(m + 8) * CH + n] = make_float2(acc[jj][2], acc[jj][3]);
        }
    }
}

// ============================================================
// Fused: reduce partials -> normalize -> softmax -> combine with proj
// -> emit fragment-permuted fp16 apm directly. (R14, unchanged.)
// ============================================================
__global__ __launch_bounds__(256) void attn_combine_kernel(
    const float* __restrict__ temperature, const float* __restrict__ P,
    uint32_t* __restrict__ apm)
{
    const int bh = blockIdx.x;
    const int b = bh >> 2, h = bh & 3;
    __shared__ float S[CH * CH];
    __shared__ float A[CH * CH];
    __shared__ float rq[CH];
    __shared__ float rk[CH];
    const int tid = threadIdx.x;
    const int lane = tid & 31, wid = tid >> 5;

    for (int e = tid; e < CH * CH; e += 256) {
        float s = 0.f;
#pragma unroll
        for (int p = 0; p < NCHUNK; p++)
            s += g_part_gram[((size_t)bh * NCHUNK + p) * CH * CH + e];
        S[e] = s;
    }
    if (tid < CH) {
        const size_t cc = (size_t)(b * C3 + h * CH + tid) * 2;
        rq[tid] = fmaxf(sqrtf(g_norm_part[cc] + g_norm_part[cc + 1]), 1e-12f);
    } else if (tid < 2 * CH) {
        const size_t cc = (size_t)(b * C3 + CDIM + h * CH + (tid - CH)) * 2;
        rk[tid - CH] = fmaxf(sqrtf(g_norm_part[cc] + g_norm_part[cc + 1]), 1e-12f);
    }
    __syncthreads();

    // warp-parallel softmax: warp w -> rows 6w..6w+5, lanes split 48 cols
    const float tmp = temperature[h];
    const int c2 = lane + 32;
#pragma unroll
    for (int rr = 0; rr < 6; rr++) {
        const int r = wid * 6 + rr;
        const float fq = tmp / rq[r];
        float v1 = S[r * CH + lane] * fq / rk[lane];
        float v2 = (c2 < CH) ? S[r * CH + c2] * fq / rk[c2] : -1e30f;
        float mx = fmaxf(v1, v2);
#pragma unroll
        for (int o = 16; o; o >>= 1) mx = fmaxf(mx, __shfl_xor_sync(0xffffffffu, mx, o));
        float e1 = expf(v1 - mx);
        float e2 = (c2 < CH) ? expf(v2 - mx) : 0.f;
        float sm = e1 + e2;
#pragma unroll
        for (int o = 16; o; o >>= 1) sm += __shfl_xor_sync(0xffffffffu, sm, o);
        float inv = 1.f / sm;
        A[r * CH + lane] = e1 * inv;
        if (c2 < CH) A[r * CH + c2] = e2 * inv;
    }
    __syncthreads();

    // combine + permute: thread m computes Comb row m for head h's 48 cols,
    // packs k-pairs to fp16 and scatters into mma fragment layout.
    if (tid < CDIM) {
        const int m = tid;
        float p[CH];
#pragma unroll
        for (int c = 0; c < CH; c++) p[c] = P[(size_t)m * CDIM + h * CH + c];
        float o[CH];
#pragma unroll 4
        for (int d = 0; d < CH; d++) {
            float s = 0.f;
#pragma unroll
            for (int c = 0; c < CH; c++) s = fmaf(p[c], A[c * CH + d], s);
            o[d] = s;
        }
        const int mt = m >> 7;
        const int m16 = (m & 127) >> 4;
        const int gg = m & 7;
        const int hi = (m & 15) >> 3;
        uint32_t* base = apm + (size_t)b * 24576 + mt * 12288 + m16 * 128;
#pragma unroll
        for (int d2 = 0; d2 < CH / 2; d2++) {
            const int k = h * CH + 2 * d2;
            const int k16 = k >> 4;
            const int rem = k & 15;
            const int t = (rem & 7) >> 1;
            const int reg = (rem >> 3) * 2 + hi;
            base[k16 * 1024 + (gg * 4 + t) * 4 + reg] = h2pack(o[2 * d2], o[2 * d2 + 1]);
        }
    }
}

// ============================================================
extern "C" void kernel_launch(void* const* d_in, const int* in_sizes, int n_in,
                              void* d_out, int out_size)
{
    const float* x      = (const float*)d_in[0];
    const float* qkv_w  = (const float*)d_in[1];
    const float* dw_w   = (const float*)d_in[2];
    const float* proj_w = (const float*)d_in[3];
    const float* temp   = (const float*)d_in[4];
    float* out = (float*)d_out;

    __half *qkv, *qkv2;
    uint32_t *apq, *apm;
    cudaGetSymbolAddress((void**)&qkv,  g_qkv);
    cudaGetSymbolAddress((void**)&qkv2, g_qkv2);
    cudaGetSymbolAddress((void**)&apq,  g_apq);
    cudaGetSymbolAddress((void**)&apm,  g_apm);

    dim3 blk(256);
    // 0) permute + fp16-convert qkv weights
    prep_a<<<60, blk>>>(qkv_w, apq, C3);
    // 1) qkv 1x1 conv (fp16 tensor cores; tile 4 takes ragged path)
    pw_mma<float, __half><<<dim3(5, 128, BATCH), blk>>>(
        apq, 0, x, (size_t)CDIM * HWD, qkv, (size_t)C3 * HWD, C3);
    // 2) depthwise 3x3 + Q/K norm partials (R14 structure)
    dw_conv_kernel<<<dim3(BATCH * C3, 2), blk>>>(qkv, dw_w, qkv2);
    // 3) Q@K^T partials (fp16 tensor cores, cp.async staging)
    gram_kernel<<<dim3(NCHUNK, BATCH * HEADS), blk>>>();
    // 4) softmax + fold into proj weights + fragment-permute (fused)
    attn_combine_kernel<<<BATCH * HEADS, blk>>>(temp, proj_w, apm);
    // 5) fused (proj @ attn) @ v -> d_out (tile 1 takes ragged path)
    pw_mma<__half, float><<<dim3(2, 128, BATCH), blk>>>(
        apm, 24576, qkv2 + (size_t)2 * CDIM * HWD, (size_t)C3 * HWD,
        out, (size_t)CDIM * HWD, CDIM);
}

// round 17
// speedup vs baseline: 1.0811x; 1.0200x over previous
#include <cuda_runtime.h>
#include <cuda_fp16.h>
#include <math.h>
#include <stdint.h>

#define BATCH 8
#define CDIM 192
#define C3 576
#define HWD 16384
#define HEADS 4
#define CH 48
#define NCHUNK 32
#define CHUNKPX 512

typedef unsigned long long ull;

// ---- fp16 mma m16n8k16, fp32 accumulate ----
__device__ __forceinline__ void mma_f16(float* c, uint4 a, uint2 b) {
    asm volatile(
        "mma.sync.aligned.m16n8k16.row.col.f32.f16.f16.f32 "
        "{%0,%1,%2,%3}, {%4,%5,%6,%7}, {%8,%9}, {%0,%1,%2,%3};"
        : "+f"(c[0]), "+f"(c[1]), "+f"(c[2]), "+f"(c[3])
        : "r"(a.x), "r"(a.y), "r"(a.z), "r"(a.w), "r"(b.x), "r"(b.y));
}
__device__ __forceinline__ uint32_t h2pack(float a, float b) {
    __half2 h = __floats2half2_rn(a, b);
    return *(uint32_t*)&h;
}

// ---- cp.async helpers ----
__device__ __forceinline__ void cp16(void* dst, const void* src) {
    uint32_t d;
    asm("{ .reg .u64 t; cvta.to.shared.u64 t, %1; cvt.u32.u64 %0, t; }" : "=r"(d) : "l"(dst));
    asm volatile("cp.async.cg.shared.global [%0], [%1], 16;" :: "r"(d), "l"(src) : "memory");
}
#define CP_COMMIT() asm volatile("cp.async.commit_group;" ::: "memory")
#define CP_WAIT(n)  asm volatile("cp.async.wait_group %0;" :: "n"(n) : "memory")

// ---- typed 4-element loads / 2-element stores ----
__device__ __forceinline__ float4 load4(const float* p) { return *(const float4*)p; }
__device__ __forceinline__ float4 load4(const __half* p) {
    __half2 h0 = *(const __half2*)p;
    __half2 h1 = *(const __half2*)(p + 2);
    float2 a = __half22float2(h0), b = __half22float2(h1);
    return make_float4(a.x, a.y, b.x, b.y);
}
__device__ __forceinline__ void store2(float* p, float a, float b) {
    *(float2*)p = make_float2(a, b);
}
__device__ __forceinline__ void store2(__half* p, float a, float b) {
    *(__half2*)p = __floats2half2_rn(a, b);
}

// ---- scratch (device globals; no allocations allowed) ----
__device__ __half g_qkv [(size_t)BATCH * C3 * HWD];
__device__ __half g_qkv2[(size_t)BATCH * C3 * HWD];
__device__ float g_part_gram[(size_t)BATCH * HEADS * NCHUNK * CH * CH];
__device__ float g_norm_part[(size_t)BATCH * C3 * 2];   // per (b,c): 2 block partials
__device__ uint32_t g_apq[5 * 12288];          // qkv W, fp16 fragment-permuted
__device__ uint32_t g_apm[BATCH * 2 * 12288];  // combined proj@attn, per batch

// ============================================================
// Permute W[M,192] into fp16 m16n8k16 fragment order.
// ============================================================
__global__ __launch_bounds__(256) void prep_a(
    const float* __restrict__ W, uint32_t* __restrict__ Ap, int Mdim)
{
    const int idx = blockIdx.x * 256 + threadIdx.x;
    const int lane = idx & 31;
    int rest = idx >> 5;
    const int m16 = rest & 7; rest >>= 3;
    const int k16 = rest % 12;
    const int mt = rest / 12;
    const int g = lane >> 2, t = lane & 3;
    const int row = mt * 128 + m16 * 16 + g;
    const int k = k16 * 16 + 2 * t;
    float a00 = 0.f, a01 = 0.f, a10 = 0.f, a11 = 0.f;
    float a20 = 0.f, a21 = 0.f, a30 = 0.f, a31 = 0.f;
    if (row < Mdim) {
        const float* wr = W + (size_t)row * CDIM + k;
        a00 = wr[0]; a01 = wr[1]; a20 = wr[8]; a21 = wr[9];
    }
    if (row + 8 < Mdim) {
        const float* wr = W + (size_t)(row + 8) * CDIM + k;
        a10 = wr[0]; a11 = wr[1]; a30 = wr[8]; a31 = wr[9];
    }
    uint4 o;
    o.x = h2pack(a00, a01); o.y = h2pack(a10, a11);
    o.z = h2pack(a20, a21); o.w = h2pack(a30, a31);
    *(uint4*)(Ap + (size_t)idx * 4) = o;
}

// ============================================================
// Pointwise GEMM via mma.sync fp16: Y[b,m,n] = sum_k A[(b),m,k] X[b,k,n]
// 128x128 block, BK=32, double buffered; A tile staged via cp.async.
// (R14 code path — unmodified; measured 311.3us end-to-end.)
// ============================================================
template <typename InT, typename OutT>
__global__ __launch_bounds__(256) void pw_mma(
    const uint32_t* __restrict__ Ap, size_t a_bstride,
    const InT* __restrict__ X, size_t x_bstride,
    OutT* __restrict__ Y, size_t y_bstride, int Mdim)
{
    __shared__ __align__(16) uint32_t As[2][2048];
    __shared__ __align__(16) uint32_t Bs16[2][16 * 136];
    const int tid = threadIdx.x;
    const int lane = tid & 31, wid = tid >> 5;
    const int mt = blockIdx.x;
    const int n0 = blockIdx.y * 128;
    const size_t boffX = (size_t)blockIdx.z * x_bstride;
    const size_t boffY = (size_t)blockIdx.z * y_bstride;

    const uint32_t* apg = Ap + (size_t)blockIdx.z * a_bstride + (size_t)mt * 12288;
    const int nq = tid & 31;
    const int bk0 = tid >> 5;

    float4 b_r0, b_r1, b_r2, b_r3;

    auto cpa_iter = [&](int it, int buf) {
        const uint32_t* ap = apg + (size_t)it * 2048 + tid * 8;
        cp16(&As[buf][tid * 8], ap);
        cp16(&As[buf][tid * 8 + 4], ap + 4);
    };
    auto ldgb_iter = [&](int it) {
        const InT* xb = X + boffX + (size_t)(it * 32 + 2 * bk0) * HWD + n0 + nq * 4;
        b_r0 = load4(xb);
        b_r1 = load4(xb + HWD);
        b_r2 = load4(xb + (size_t)16 * HWD);
        b_r3 = load4(xb + (size_t)17 * HWD);
    };
    auto stsb_iter = [&](int buf) {
        uint4 p0, p1;
        p0.x = h2pack(b_r0.x, b_r1.x); p0.y = h2pack(b_r0.y, b_r1.y);
        p0.z = h2pack(b_r0.z, b_r1.z); p0.w = h2pack(b_r0.w, b_r1.w);
        p1.x = h2pack(b_r2.x, b_r3.x); p1.y = h2pack(b_r2.y, b_r3.y);
        p1.z = h2pack(b_r2.z, b_r3.z); p1.w = h2pack(b_r2.w, b_r3.w);
        *(uint4*)&Bs16[buf][bk0 * 136 + nq * 4] = p0;
        *(uint4*)&Bs16[buf][(8 + bk0) * 136 + nq * 4] = p1;
    };

    float acc[2][8][4];
#pragma unroll
    for (int f = 0; f < 2; f++)
#pragma unroll
        for (int j = 0; j < 8; j++)
#pragma unroll
            for (int e = 0; e < 4; e++) acc[f][j][e] = 0.f;

    const int m16a = (wid & 3) * 2;
    const int t = lane & 3;
    const int g = lane >> 2;
    const int nwb = (wid >> 2) * 64;

    auto compute = [&](int buf) {
#pragma unroll
        for (int s = 0; s < 2; s++) {
            uint4 A0 = *(const uint4*)&As[buf][(s * 256 + m16a * 32 + lane) * 4];
            uint4 A1 = *(const uint4*)&As[buf][(s * 256 + (m16a + 1) * 32 + lane) * 4];
            const int br0 = (s * 8 + t) * 136 + nwb + g;
            const int br1 = (s * 8 + t + 4) * 136 + nwb + g;
#pragma unroll
            for (int j = 0; j < 8; j++) {
                uint2 b = make_uint2(Bs16[buf][br0 + j * 8], Bs16[buf][br1 + j * 8]);
                mma_f16(acc[0][j], A0, b);
                mma_f16(acc[1][j], A1, b);
            }
        }
    };

    cpa_iter(0, 0);
    ldgb_iter(0);
    CP_COMMIT();
    stsb_iter(0);
    CP_WAIT(0);
    __syncthreads();
#pragma unroll 1
    for (int it = 0; it < 6; it++) {
        if (it + 1 < 6) {
            cpa_iter(it + 1, (it + 1) & 1);
            ldgb_iter(it + 1);
            CP_COMMIT();
        }
        compute(it & 1);
        if (it + 1 < 6) stsb_iter((it + 1) & 1);
        CP_WAIT(0);
        __syncthreads();
    }

    const int mw = mt * 128 + (wid & 3) * 32;
#pragma unroll
    for (int f = 0; f < 2; f++) {
        const int m = mw + f * 16 + g;
#pragma unroll
        for (int j = 0; j < 8; j++) {
            OutT* p = Y + boffY + (size_t)m * HWD + n0 + nwb + j * 8 + 2 * t;
            if (m < Mdim)
                store2(p, acc[f][j][0], acc[f][j][1]);
            if (m + 8 < Mdim)
                store2(p + (size_t)8 * HWD, acc[f][j][2], acc[f][j][3]);
        }
    }
}

// ============================================================
// Depthwise 3x3, pad 1 — register sliding window + shuffle halos.
// 8-row warp strips, grid (BATCH*C3, 2). Emits per-channel
// sum-of-squares partials (fp32, deterministic) for Q/K channels.
// ============================================================
__global__ __launch_bounds__(256) void dw_conv_kernel(
    const __half* __restrict__ in, const float* __restrict__ wts,
    __half* __restrict__ out)
{
    const int bc = blockIdx.x;
    const int c = bc % C3;
    const int warp = threadIdx.x >> 5;
    const int lane = threadIdx.x & 31;
    const int y0 = blockIdx.y * 64 + warp * 8;

    float w[9];
#pragma unroll
    for (int i = 0; i < 9; i++) w[i] = __ldg(wts + c * 9 + i);

    const __half* ip = in + (size_t)bc * HWD + lane * 4;
    float win[3][6];

    auto loadrow = [&](int gy, float* row6) {
        float4 v = make_float4(0.f, 0.f, 0.f, 0.f);
        if (gy >= 0 && gy < 128) v = load4(ip + (size_t)gy * 128);
        float l = __shfl_up_sync(0xffffffffu, v.w, 1);
        float r = __shfl_down_sync(0xffffffffu, v.x, 1);
        if (lane == 0)  l = 0.f;
        if (lane == 31) r = 0.f;
        row6[0] = l; row6[1] = v.x; row6[2] = v.y;
        row6[3] = v.z; row6[4] = v.w; row6[5] = r;
    };

    loadrow(y0 - 1, win[0]);
    loadrow(y0,     win[1]);
    __half* op = out + (size_t)bc * HWD + lane * 4;
    float ns = 0.f;
#pragma unroll
    for (int r = 0; r < 8; r++) {
        loadrow(y0 + 1 + r, win[(r + 2) % 3]);
        const float* tp = win[r % 3];
        const float* mp = win[(r + 1) % 3];
        const float* bp = win[(r + 2) % 3];
        float o[4];
#pragma unroll
        for (int p = 0; p < 4; p++) {
            float s = 0.f;
            s = fmaf(tp[p], w[0], s); s = fmaf(tp[p + 1], w[1], s); s = fmaf(tp[p + 2], w[2], s);
            s = fmaf(mp[p], w[3], s); s = fmaf(mp[p + 1], w[4], s); s = fmaf(mp[p + 2], w[5], s);
            s = fmaf(bp[p], w[6], s); s = fmaf(bp[p + 1], w[7], s); s = fmaf(bp[p + 2], w[8], s);
            o[p] = s;
            ns = fmaf(s, s, ns);
        }
        __half2 h0 = __floats2half2_rn(o[0], o[1]);
        __half2 h1 = __floats2half2_rn(o[2], o[3]);
        __half2* dst = (__half2*)(op + (size_t)(y0 + r) * 128);
        dst[0] = h0; dst[1] = h1;
    }

    // deterministic block reduction of sum-of-squares (Q/K channels only)
    if (c < 2 * CDIM) {
        __shared__ float red[8];
#pragma unroll
        for (int o = 16; o; o >>= 1) ns += __shfl_xor_sync(0xffffffffu, ns, o);
        if (lane == 0) red[warp] = ns;
        __syncthreads();
        if (threadIdx.x == 0) {
            float s = 0.f;
#pragma unroll
            for (int i = 0; i < 8; i++) s += red[i];
            g_norm_part[(size_t)bc * 2 + blockIdx.y] = s;
        }
    }
}

// ============================================================
// Gram on fp16 tensor cores: Q@K^T (48x48) per (bh, 512-px chunk).
// cp.async raw staging, double-buffered.
// ============================================================
__global__ __launch_bounds__(256) void gram_kernel()
{
    const int chunk = blockIdx.x;
    const int bh = blockIdx.y;
    const int b = bh >> 2, h = bh & 3;
    const __half* qb = g_qkv2 + ((size_t)b * C3 + h * CH) * HWD;
    const __half* kb = g_qkv2 + ((size_t)b * C3 + CDIM + h * CH) * HWD;
    __shared__ __align__(16) __half Qs[2][CH][72];
    __shared__ __align__(16) __half Ks[2][CH][72];
    const int tid = threadIdx.x;
    const int lane = tid & 31, wid = tid >> 5;
    const int n0 = chunk * CHUNKPX;

    float acc[3][4];
#pragma unroll
    for (int jj = 0; jj < 3; jj++)
#pragma unroll
        for (int e = 0; e < 4; e++) acc[jj][e] = 0.f;

    const int mrow = wid % 3;
    const int nhalf = (wid < 6) ? (wid / 3) : 0;
    const int g = lane >> 2, t = lane & 3;

    const __half* sbase = (tid < 128) ? qb : kb;
    const int st = tid & 127;

    auto stage = [&](int t0, int buf) {
        __half (*dst)[72] = (tid < 128) ? Qs[buf] : Ks[buf];
#pragma unroll
        for (int i = 0; i < 3; i++) {
            int idx = i * 128 + st;
            int row = idx >> 3, cg = idx & 7;
            cp16(&dst[row][cg * 8], sbase + (size_t)row * HWD + n0 + t0 + cg * 8);
        }
    };

    const int NTILE = CHUNKPX / 64;
    stage(0, 0);
    CP_COMMIT();
#pragma unroll 1
    for (int ti = 0; ti < NTILE; ti++) {
        if (ti + 1 < NTILE) {
            stage((ti + 1) * 64, (ti + 1) & 1);
            CP_COMMIT();
            CP_WAIT(1);
        } else {
            CP_WAIT(0);
        }
        __syncthreads();
        if (wid < 6) {
            const int buf = ti & 1;
            const int mr = 16 * mrow + g;
#pragma unroll
            for (int s = 0; s < 4; s++) {
                const int kh = s * 16 + 2 * t;
                uint4 a;
                a.x = *(const uint32_t*)&Qs[buf][mr][kh];
                a.y = *(const uint32_t*)&Qs[buf][mr + 8][kh];
                a.z = *(const uint32_t*)&Qs[buf][mr][kh + 8];
                a.w = *(const uint32_t*)&Qs[buf][mr + 8][kh + 8];
#pragma unroll
                for (int jj = 0; jj < 3; jj++) {
                    const int nr = 8 * (3 * nhalf + jj) + g;
                    uint2 bf = make_uint2(*(const uint32_t*)&Ks[buf][nr][kh],
                                          *(const uint32_t*)&Ks[buf][nr][kh + 8]);
                    mma_f16(acc[jj], a, bf);
                }
            }
        }
        __syncthreads();
    }

    if (wid < 6) {
        float* gp = g_part_gram + ((size_t)bh * NCHUNK + chunk) * CH * CH;
        const int m = 16 * mrow + g;
#pragma unroll
        for (int jj = 0; jj < 3; jj++) {
            const int n = 8 * (3 * nhalf + jj) + 2 * t;
            *(float2*)&gp[m * CH + n] = make_float2(acc[jj][0], acc[jj][1]);
            *(float2*)&gp[(m + 8) * CH + n] = make_float2(acc[jj][2], acc[jj][3]);
        }
    }
}

// ============================================================
// Fused: reduce partials -> normalize -> softmax -> combine with proj
// -> emit fragment-permuted fp16 apm directly.
// ============================================================
__global__ __launch_bounds__(256) void attn_combine_kernel(
    const float* __restrict__ temperature, const float* __restrict__ P,
    uint32_t* __restrict__ apm)
{
    const int bh = blockIdx.x;
    const int b = bh >> 2, h = bh & 3;
    __shared__ float S[CH * CH];
    __shared__ float A[CH * CH];
    __shared__ float rq[CH];
    __shared__ float rk[CH];
    const int tid = threadIdx.x;
    const int lane = tid & 31, wid = tid >> 5;

    for (int e = tid; e < CH * CH; e += 256) {
        float s = 0.f;
#pragma unroll
        for (int p = 0; p < NCHUNK; p++)
            s += g_part_gram[((size_t)bh * NCHUNK + p) * CH * CH + e];
        S[e] = s;
    }
    if (tid < CH) {
        const size_t cc = (size_t)(b * C3 + h * CH + tid) * 2;
        rq[tid] = fmaxf(sqrtf(g_norm_part[cc] + g_norm_part[cc + 1]), 1e-12f);
    } else if (tid < 2 * CH) {
        const size_t cc = (size_t)(b * C3 + CDIM + h * CH + (tid - CH)) * 2;
        rk[tid - CH] = fmaxf(sqrtf(g_norm_part[cc] + g_norm_part[cc + 1]), 1e-12f);
    }
    __syncthreads();

    // warp-parallel softmax: warp w -> rows 6w..6w+5, lanes split 48 cols
    const float tmp = temperature[h];
    const int c2 = lane + 32;
#pragma unroll
    for (int rr = 0; rr < 6; rr++) {
        const int r = wid * 6 + rr;
        const float fq = tmp / rq[r];
        float v1 = S[r * CH + lane] * fq / rk[lane];
        float v2 = (c2 < CH) ? S[r * CH + c2] * fq / rk[c2] : -1e30f;
        float mx = fmaxf(v1, v2);
#pragma unroll
        for (int o = 16; o; o >>= 1) mx = fmaxf(mx, __shfl_xor_sync(0xffffffffu, mx, o));
        float e1 = expf(v1 - mx);
        float e2 = (c2 < CH) ? expf(v2 - mx) : 0.f;
        float sm = e1 + e2;
#pragma unroll
        for (int o = 16; o; o >>= 1) sm += __shfl_xor_sync(0xffffffffu, sm, o);
        float inv = 1.f / sm;
        A[r * CH + lane] = e1 * inv;
        if (c2 < CH) A[r * CH + c2] = e2 * inv;
    }
    __syncthreads();

    // combine + permute: thread m computes Comb row m for head h's 48 cols,
    // packs k-pairs to fp16 and scatters into mma fragment layout.
    if (tid < CDIM) {
        const int m = tid;
        float p[CH];
#pragma unroll
        for (int c = 0; c < CH; c++) p[c] = P[(size_t)m * CDIM + h * CH + c];
        float o[CH];
#pragma unroll 4
        for (int d = 0; d < CH; d++) {
            float s = 0.f;
#pragma unroll
            for (int c = 0; c < CH; c++) s = fmaf(p[c], A[c * CH + d], s);
            o[d] = s;
        }
        const int mt = m >> 7;
        const int m16 = (m & 127) >> 4;
        const int gg = m & 7;
        const int hi = (m & 15) >> 3;
        uint32_t* base = apm + (size_t)b * 24576 + mt * 12288 + m16 * 128;
#pragma unroll
        for (int d2 = 0; d2 < CH / 2; d2++) {
            const int k = h * CH + 2 * d2;
            const int k16 = k >> 4;
            const int rem = k & 15;
            const int t = (rem & 7) >> 1;
            const int reg = (rem >> 3) * 2 + hi;
            base[k16 * 1024 + (gg * 4 + t) * 4 + reg] = h2pack(o[2 * d2], o[2 * d2 + 1]);
        }
    }
}

// ============================================================
extern "C" void kernel_launch(void* const* d_in, const int* in_sizes, int n_in,
                              void* d_out, int out_size)
{
    const float* x      = (const float*)d_in[0];
    const float* qkv_w  = (const float*)d_in[1];
    const float* dw_w   = (const float*)d_in[2];
    const float* proj_w = (const float*)d_in[3];
    const float* temp   = (const float*)d_in[4];
    float* out = (float*)d_out;

    __half *qkv, *qkv2;
    uint32_t *apq, *apm;
    cudaGetSymbolAddress((void**)&qkv,  g_qkv);
    cudaGetSymbolAddress((void**)&qkv2, g_qkv2);
    cudaGetSymbolAddress((void**)&apq,  g_apq);
    cudaGetSymbolAddress((void**)&apm,  g_apm);

    dim3 blk(256);
    // 0) permute + fp16-convert qkv weights
    prep_a<<<60, blk>>>(qkv_w, apq, C3);
    // 1) qkv 1x1 conv (fp16 tensor cores, cp.async A)
    pw_mma<float, __half><<<dim3(5, 128, BATCH), blk>>>(
        apq, 0, x, (size_t)CDIM * HWD, qkv, (size_t)C3 * HWD, C3);
    // 2) depthwise 3x3 + Q/K norm partials
    dw_conv_kernel<<<dim3(BATCH * C3, 2), blk>>>(qkv, dw_w, qkv2);
    // 3) Q@K^T partials (fp16 tensor cores, cp.async staging)
    gram_kernel<<<dim3(NCHUNK, BATCH * HEADS), blk>>>();
    // 4) softmax + fold into proj weights + fragment-permute (fused)
    attn_combine_kernel<<<BATCH * HEADS, blk>>>(temp, proj_w, apm);
    // 5) fused (proj @ attn) @ v -> d_out
    pw_mma<__half, float><<<dim3(2, 128, BATCH), blk>>>(
        apm, 24576, qkv2 + (size_t)2 * CDIM * HWD, (size_t)C3 * HWD,
        out, (size_t)CDIM * HWD, CDIM);
}